// round 12
// baseline (speedup 1.0000x reference)
#include <cuda_runtime.h>
#include <cuda_fp16.h>
#include <cstdint>

#define BB 128   // batch
#define PP 196   // pixels
#define EE 1024  // encoder dim
#define DD 512   // decoder hidden
#define AA 512   // attention hidden
#define TT 128   // token emb
#define VV 1000  // vocab
#define SS 256   // steps
#define LL 257   // latex length

#define NBLK 128
#define NTHR 256

#define AS2_STRIDE 36
#define WS2_STRIDE 72
#define POOL_U32 (32 * AS2_STRIDE + 32 * WS2_STRIDE)   // 3456 u32 = 13.8 KB static

// dynamic smem: ench cache (50176 u32) + s_dec(512f) + s_wa(512f) + s_attn(208f) + s_red(16f)
#define ENCH_U32 50176
#define DYN_U32 (ENCH_U32 + 512 + 512 + 208 + 16)
#define DYN_BYTES (DYN_U32 * 4)

// ---------------- device-global scratch (static, no allocation) ----------------
__device__ __align__(16) __half g_ench[(long)BB * PP * AA];    // 25.7 MB enc_t fp16
__device__ __align__(16) __half g_feath[(long)BB * PP * EE];   // 51.5 MB features fp16
__device__ __align__(16) __half g_hist[(long)SS * BB * DD];    // 33.5 MB h2 history (fp16)
__device__ float g_mean[BB * EE];
__device__ float g_hc[BB * 2 * DD];
__device__ float g_c1[BB * DD], g_c2[BB * DD];
__device__ float g_dec[BB * AA];
// half2-k-packed activations
__device__ __align__(16) __half g_x1h[BB * 1664];   // [emb 0..127 | awe 128..1151 | h1 1152..1663]
__device__ __align__(16) __half g_x2h[BB * 1024];   // [h1n 0..511 | h2 512..1023]
// fp16 weights, half2-packed along k, u32 layout [K/2][NCOLS]
// W1h/W2h col permutation: storage col m: jj=m>>6, g=(m>>4)&3, dl=m&15 <-> gate row g*512+jj*16+dl
__device__ __align__(16) __half g_W1h[1664 * 2048];   // 6.8 MB
__device__ __align__(16) __half g_W2h[1024 * 2048];   // 4 MB
__device__ __align__(16) __half g_Wfdh[512 * 1536];   // cols: Wf(1000) | Wdec(512) | pad(24)
__device__ __align__(16) __half g_Weth[EE * AA];      // enc weights fp16
__device__ float g_Whct[EE * 2 * DD];                 // Wh0 | Wc0 fp32
__device__ float g_b1[2048], g_b2[2048], g_bfd[1536], g_bhc[2 * DD];

// tree-barrier state (padded counters on distinct L2 lines; monotonic gen -> replay safe)
__device__ unsigned g_cnt4[128];   // group g uses g_cnt4[g*32]
__device__ unsigned g_root = 0;
__device__ unsigned g_gen = 0;

__device__ __forceinline__ float tanh_fast(float x) {
    float y;
    asm("tanh.approx.f32 %0, %1;" : "=f"(y) : "f"(x));
    return y;
}
__device__ __forceinline__ float sigmoidf(float x) {
    return 1.0f / (1.0f + __expf(-x));
}
__device__ __forceinline__ uint32_t pack_h2(float a, float b) {
    __half2 h = __floats2half2_rn(a, b);
    return *reinterpret_cast<uint32_t*>(&h);
}

__device__ __forceinline__ void grid_barrier() {
    __syncthreads();
    if (threadIdx.x == 0) {
        __threadfence();
        unsigned gen = *(volatile unsigned*)&g_gen;   // read BEFORE arriving
        bool releaser = false;
        if (atomicAdd(&g_cnt4[(blockIdx.x & 3) * 32], 1u) == 31u) {
            if (atomicAdd(&g_root, 1u) == 3u) {
                atomicExch(&g_cnt4[0], 0u);
                atomicExch(&g_cnt4[32], 0u);
                atomicExch(&g_cnt4[64], 0u);
                atomicExch(&g_cnt4[96], 0u);
                atomicExch(&g_root, 0u);
                __threadfence();
                atomicAdd(&g_gen, 1u);
                releaser = true;
            }
        }
        if (!releaser) {
            // two-tier wait: bounded pure spin (fast wake), then nanosleep fallback
            int spins = 0;
            while (*(volatile unsigned*)&g_gen == gen) {
                if (++spins > 4096) __nanosleep(64);
            }
        }
        __threadfence();
    }
    __syncthreads();
}

// ---------------- weight transposes + bias combine ----------------
__global__ void prep_kernel(const float* __restrict__ W1ih, const float* __restrict__ W1hh,
                            const float* __restrict__ W2ih, const float* __restrict__ W2hh,
                            const float* __restrict__ Wf, const float* __restrict__ Wdec,
                            const float* __restrict__ Wenc, const float* __restrict__ Wh0,
                            const float* __restrict__ Wc0,
                            const float* __restrict__ b1ih, const float* __restrict__ b1hh,
                            const float* __restrict__ b2ih, const float* __restrict__ b2hh,
                            const float* __restrict__ bf, const float* __restrict__ bdec,
                            const float* __restrict__ bh0, const float* __restrict__ bc0) {
    long tid = (long)blockIdx.x * blockDim.x + threadIdx.x;
    long nt = (long)gridDim.x * blockDim.x;
    for (long i = tid; i < 1664L * 2048; i += nt) {
        int k = (int)(i >> 11), m = (int)(i & 2047);
        int jj = m >> 6, g = (m >> 4) & 3, dl = m & 15;
        int r = g * 512 + jj * 16 + dl;
        float v = (k < 1152) ? W1ih[(long)r * 1152 + k] : W1hh[(long)r * 512 + (k - 1152)];
        g_W1h[((long)(k >> 1) * 2048 + m) * 2 + (k & 1)] = __float2half(v);
    }
    for (long i = tid; i < 1024L * 2048; i += nt) {
        int k = (int)(i >> 11), m = (int)(i & 2047);
        int jj = m >> 6, g = (m >> 4) & 3, dl = m & 15;
        int r = g * 512 + jj * 16 + dl;
        float v = (k < 512) ? W2ih[(long)r * 512 + k] : W2hh[(long)r * 512 + (k - 512)];
        g_W2h[((long)(k >> 1) * 2048 + m) * 2 + (k & 1)] = __float2half(v);
    }
    for (long i = tid; i < 512L * 1536; i += nt) {
        int k = (int)(i / 1536), n = (int)(i % 1536);
        float v = 0.f;
        if (n < 1000) v = Wf[(long)n * 512 + k];
        else if (n < 1512) v = Wdec[(long)(n - 1000) * 512 + k];
        g_Wfdh[((long)(k >> 1) * 1536 + n) * 2 + (k & 1)] = __float2half(v);
    }
    for (long i = tid; i < (long)EE * AA; i += nt) {
        int e = (int)(i >> 9), a = (int)(i & 511);
        g_Weth[((long)(e >> 1) * 512 + a) * 2 + (e & 1)] = __float2half(Wenc[(long)a * EE + e]);
    }
    for (long i = tid; i < (long)EE * 1024; i += nt) {
        int e = (int)(i >> 10), j = (int)(i & 1023);
        g_Whct[i] = (j < 512) ? Wh0[(long)j * EE + e] : Wc0[(long)(j - 512) * EE + e];
    }
    for (long i = tid; i < 2048; i += nt) {
        g_b1[i] = b1ih[i] + b1hh[i];
        g_b2[i] = b2ih[i] + b2hh[i];
    }
    for (long i = tid; i < 1536; i += nt)
        g_bfd[i] = (i < 1000) ? bf[i] : (i < 1512 ? bdec[i - 1000] : 0.f);
    for (long i = tid; i < 1024; i += nt)
        g_bhc[i] = (i < 512) ? bh0[i] : bc0[i - 512];
}

__global__ void featconv_kernel(const float* __restrict__ feat) {
    long tid = (long)blockIdx.x * blockDim.x + threadIdx.x;
    long nt = (long)gridDim.x * blockDim.x;
    uint32_t* out = (uint32_t*)g_feath;
    long n = (long)BB * PP * EE / 2;
    for (long i = tid; i < n; i += nt) {
        float2 f = *(const float2*)(feat + i * 2);
        out[i] = pack_h2(f.x, f.y);
    }
}

__global__ void mean_kernel(const float* __restrict__ feat) {
    int b = blockIdx.x, t = threadIdx.x;
    for (int e = t; e < EE; e += 256) {
        float acc = 0.f;
        const float* fb = feat + (long)b * PP * EE + e;
        for (int p = 0; p < PP; p++) acc += fb[(long)p * EE];
        g_mean[b * EE + e] = acc * (1.0f / 196.0f);
    }
}

// h0/c0 spread: c fp32 states; h as halves into x2h-front (h1 role) and hist slot 0 (h2 role)
__global__ void init_kernel() {
    int b = blockIdx.x, d = threadIdx.x;
    float h = g_hc[b * 1024 + d];
    float c = g_hc[b * 1024 + 512 + d];
    g_c1[b * 512 + d] = c;
    g_c2[b * 512 + d] = c;
    g_x2h[b * 1024 + d] = __float2half(h);   // h1 init (x2h front)
    g_hist[b * 512 + d] = __float2half(h);   // h2 init (hist slot 0)
}

// ---------------- fp32 SGEMM (prologue h0/c0 only) ----------------
__global__ __launch_bounds__(128)
void gemm_kernel(const float* __restrict__ Amat, int lda,
                 const float* __restrict__ W, int ldw,
                 const float* __restrict__ bias,
                 float* __restrict__ out1, long ldc1,
                 int N, int K) {
    __shared__ float As[32][128];
    __shared__ float Ws[32][16];
    int t = threadIdx.x;
    int n0 = blockIdx.x * 16;
    long m0 = (long)blockIdx.y * 128;
    int tr = t >> 2, tc = t & 3;
    int wk = t >> 2, wn = (t & 3) * 4;

    float acc[4][4];
#pragma unroll
    for (int i = 0; i < 4; i++)
#pragma unroll
        for (int j = 0; j < 4; j++) acc[i][j] = 0.f;

    for (int k0 = 0; k0 < K; k0 += 32) {
        const float4* Ap = (const float4*)(Amat + (m0 + t) * (long)lda + k0);
#pragma unroll
        for (int q = 0; q < 8; q++) {
            float4 a4 = Ap[q];
            As[q * 4 + 0][t] = a4.x;
            As[q * 4 + 1][t] = a4.y;
            As[q * 4 + 2][t] = a4.z;
            As[q * 4 + 3][t] = a4.w;
        }
        {
            float4 w4 = *(const float4*)(W + (long)(k0 + wk) * ldw + n0 + wn);
            *(float4*)&Ws[wk][wn] = w4;
        }
        __syncthreads();
#pragma unroll
        for (int k = 0; k < 32; k++) {
            float4 a4 = *(const float4*)&As[k][tr << 2];
            float4 w4 = *(const float4*)&Ws[k][tc << 2];
            float av[4] = {a4.x, a4.y, a4.z, a4.w};
            float wv[4] = {w4.x, w4.y, w4.z, w4.w};
#pragma unroll
            for (int i = 0; i < 4; i++)
#pragma unroll
                for (int j = 0; j < 4; j++) acc[i][j] += av[i] * wv[j];
        }
        __syncthreads();
    }
#pragma unroll
    for (int i = 0; i < 4; i++) {
        long m = m0 + (tr << 2) + i;
#pragma unroll
        for (int j = 0; j < 4; j++) {
            int n = n0 + (tc << 2) + j;
            if (n < N) out1[m * ldc1 + n] = acc[i][j] + bias[n];
        }
    }
}

// ================= fp16 MMA tile: C[32 x 64] = A[32 x K] @ W[K x 64slice] =================
__device__ __forceinline__ void mma32x64(const uint32_t* __restrict__ A2, int lda2, int mbase,
                                         const uint32_t* __restrict__ W2, int ldw2, int jbase,
                                         int K2, uint32_t* pool, float acc[2][4]) {
    uint32_t* As2 = pool;
    uint32_t* Ws2 = pool + 32 * AS2_STRIDE;
    const int t = threadIdx.x;
    const int warp = t >> 5, lane = t & 31;
    const int mw = warp >> 2, nw = warp & 3;
    const int gid = lane >> 2, tq = lane & 3;
    const int arow = t >> 3, ak = (t & 7) * 4;
    const int wk = t >> 3, wc = (t & 7) * 8;

#pragma unroll
    for (int nf = 0; nf < 2; nf++)
#pragma unroll
        for (int c = 0; c < 4; c++) acc[nf][c] = 0.f;

    uint4 aP = *(const uint4*)(A2 + (long)(mbase + arow) * lda2 + ak);
    uint4 wP0 = *(const uint4*)(W2 + (long)wk * ldw2 + jbase + wc);
    uint4 wP1 = *(const uint4*)(W2 + (long)wk * ldw2 + jbase + wc + 4);

    const int nT = K2 >> 5;
    for (int tile = 0; tile < nT; tile++) {
        *(uint4*)&As2[arow * AS2_STRIDE + ak] = aP;
        *(uint4*)&Ws2[wk * WS2_STRIDE + wc] = wP0;
        *(uint4*)&Ws2[wk * WS2_STRIDE + wc + 4] = wP1;
        if (tile + 1 < nT) {
            int kb = (tile + 1) * 32;
            aP = *(const uint4*)(A2 + (long)(mbase + arow) * lda2 + kb + ak);
            wP0 = *(const uint4*)(W2 + (long)(kb + wk) * ldw2 + jbase + wc);
            wP1 = *(const uint4*)(W2 + (long)(kb + wk) * ldw2 + jbase + wc + 4);
        }
        __syncthreads();
#pragma unroll
        for (int kk = 0; kk < 32; kk += 8) {
            int r = mw * 16 + gid;
            uint32_t a0 = As2[r * AS2_STRIDE + kk + tq];
            uint32_t a1 = As2[(r + 8) * AS2_STRIDE + kk + tq];
            uint32_t a2 = As2[r * AS2_STRIDE + kk + 4 + tq];
            uint32_t a3 = As2[(r + 8) * AS2_STRIDE + kk + 4 + tq];
#pragma unroll
            for (int nf = 0; nf < 2; nf++) {
                int cc = nw * 16 + nf * 8 + gid;
                uint32_t b0 = Ws2[(kk + tq) * WS2_STRIDE + cc];
                uint32_t b1 = Ws2[(kk + 4 + tq) * WS2_STRIDE + cc];
                asm volatile(
                    "mma.sync.aligned.m16n8k16.row.col.f32.f16.f16.f32 "
                    "{%0,%1,%2,%3}, {%4,%5,%6,%7}, {%8,%9}, {%0,%1,%2,%3};"
                    : "+f"(acc[nf][0]), "+f"(acc[nf][1]), "+f"(acc[nf][2]), "+f"(acc[nf][3])
                    : "r"(a0), "r"(a1), "r"(a2), "r"(a3), "r"(b0), "r"(b1));
            }
        }
        __syncthreads();
    }
}

// ================= gates GEMM + fused LSTM cell =================
// block (jj=bid>>2, mi=bid&3): batches mi*32..+31, hidden dims jj*16..+15
__device__ __forceinline__ void lstm_phase(const __half* __restrict__ Ah, int lda2,
                                           const __half* __restrict__ Wh,
                                           const float* __restrict__ bias, int K2,
                                           float* __restrict__ cst,
                                           __half* __restrict__ hcopy_h, int hstride,
                                           uint32_t* pool) {
    const int t = threadIdx.x;
    const int jj = blockIdx.x >> 2, mi = blockIdx.x & 3;
    const int mbase = mi * 32;
    const int warp = t >> 5, lane = t & 31;
    const int mw = warp >> 2, nw = warp & 3;
    const int gid = lane >> 2, tq = lane & 3;

    float acc[2][4];
    mma32x64((const uint32_t*)Ah, lda2, mbase, (const uint32_t*)Wh, 2048, jj * 64, K2, pool, acc);

    float* sg = (float*)pool;   // [32][65]
#pragma unroll
    for (int nf = 0; nf < 2; nf++)
#pragma unroll
        for (int c = 0; c < 4; c++) {
            int row = mw * 16 + gid + ((c & 2) ? 8 : 0);
            int col = nw * 16 + nf * 8 + 2 * tq + (c & 1);
            sg[row * 65 + col] = acc[nf][c];
        }
    __syncthreads();
#pragma unroll
    for (int r = 0; r < 2; r++) {
        int idx = t + 256 * r;
        int bl = idx >> 4, dl = idx & 15;
        int b = mbase + bl;
        int d = jj * 16 + dl;
        float gi = sg[bl * 65 + 0 + dl]  + bias[0 * 512 + d];
        float gf = sg[bl * 65 + 16 + dl] + bias[1 * 512 + d];
        float gg = sg[bl * 65 + 32 + dl] + bias[2 * 512 + d];
        float go = sg[bl * 65 + 48 + dl] + bias[3 * 512 + d];
        float cn = sigmoidf(gf) * cst[b * 512 + d] + sigmoidf(gi) * tanhf(gg);
        float hn = sigmoidf(go) * tanhf(cn);
        cst[b * 512 + d] = cn;
        hcopy_h[(long)b * hstride + d] = __float2half(hn);
    }
    __syncthreads();
}

// ================= dec-only GEMM: dec = h2 @ Wdec + bdec (32 blocks) =================
__device__ __forceinline__ void ddec_phase(int slot, uint32_t* pool) {
    const int bid = blockIdx.x;
    if (bid >= 32) return;
    const int t = threadIdx.x;
    const int jj = bid >> 2, mi = bid & 3;
    const int warp = t >> 5, lane = t & 31;
    const int mw = warp >> 2, nw = warp & 3;
    const int gid = lane >> 2, tq = lane & 3;

    float acc[2][4];
    mma32x64((const uint32_t*)g_hist + (long)slot * 32768, 256, mi * 32,
             (const uint32_t*)g_Wfdh, 1536, 1000 + jj * 64, 256, pool, acc);

#pragma unroll
    for (int nf = 0; nf < 2; nf++)
#pragma unroll
        for (int c = 0; c < 4; c++) {
            int m = mi * 32 + mw * 16 + gid + ((c & 2) ? 8 : 0);
            int col = jj * 64 + nw * 16 + nf * 8 + 2 * tq + (c & 1);   // 0..511
            g_dec[m * 512 + col] = acc[nf][c] + g_bfd[1000 + col];
        }
}

// ================= epilogue: preds[b][s][:] = hist[s][b] @ Wf + bf =================
__global__ __launch_bounds__(NTHR)
void preds_kernel(float* __restrict__ preds) {
    __shared__ __align__(16) uint32_t pool[POOL_U32];
    const int t = threadIdx.x;
    const int jj = blockIdx.x;          // 16 (cols jj*64..+63; >=1000 masked)
    const int mt = blockIdx.y;          // 1024 (rows mt*32..+31 of 32768)
    const int warp = t >> 5, lane = t & 31;
    const int mw = warp >> 2, nw = warp & 3;
    const int gid = lane >> 2, tq = lane & 3;

    float acc[2][4];
    mma32x64((const uint32_t*)g_hist, 256, mt * 32,
             (const uint32_t*)g_Wfdh, 1536, jj * 64, 256, pool, acc);

#pragma unroll
    for (int nf = 0; nf < 2; nf++)
#pragma unroll
        for (int c = 0; c < 4; c++) {
            int m = mt * 32 + mw * 16 + gid + ((c & 2) ? 8 : 0);
            int col = jj * 64 + nw * 16 + nf * 8 + 2 * tq + (c & 1);
            if (col < 1000) {
                int s = m >> 7, b = m & 127;
                preds[((long)b * SS + s) * VV + col] = acc[nf][c] + g_bfd[col];
            }
        }
}

// ================= prologue enc GEMM: ench = feath @ Weth + benc =================
__global__ __launch_bounds__(NTHR)
void enc_mma_kernel(const float* __restrict__ benc) {
    __shared__ __align__(16) uint32_t pool[POOL_U32];
    const int t = threadIdx.x;
    const int jj = blockIdx.x;          // 8
    const int mt = blockIdx.y;          // 784
    const int warp = t >> 5, lane = t & 31;
    const int mw = warp >> 2, nw = warp & 3;
    const int gid = lane >> 2, tq = lane & 3;

    float acc[2][4];
    mma32x64((const uint32_t*)g_feath, 512, mt * 32, (const uint32_t*)g_Weth, 512, jj * 64,
             512, pool, acc);

    uint32_t* out = (uint32_t*)g_ench;
#pragma unroll
    for (int nf = 0; nf < 2; nf++) {
        int cb = jj * 64 + nw * 16 + nf * 8 + 2 * tq;
        int r0 = mt * 32 + mw * 16 + gid;
        out[(long)r0 * 256 + (cb >> 1)] =
            pack_h2(acc[nf][0] + benc[cb], acc[nf][1] + benc[cb + 1]);
        out[(long)(r0 + 8) * 256 + (cb >> 1)] =
            pack_h2(acc[nf][2] + benc[cb], acc[nf][3] + benc[cb + 1]);
    }
}

// ================= persistent decoder kernel =================
__global__ __launch_bounds__(NTHR, 1)
void decoder_kernel(const int* __restrict__ latex, const float* __restrict__ emb,
                    const float* __restrict__ Wattn, float* __restrict__ alphas) {
    extern __shared__ __align__(16) uint32_t dyn[];
    __shared__ __align__(16) uint32_t pool[POOL_U32];
    uint32_t* sE = dyn;                          // ench cache [196][256] u32
    float* s_dec  = (float*)(dyn + ENCH_U32);    // 512
    float* s_wa   = s_dec + 512;                 // 512
    float* s_attn = s_wa + 512;                  // 208
    float* s_red  = s_attn + 208;                // 16
    const int t = threadIdx.x;
    const int bid = blockIdx.x;
    const int warp = t >> 5, lane = t & 31;
    const uint32_t* histu = (const uint32_t*)g_hist;

    // one-time: cache this batch's enc_t slice + Wattn in smem
    {
        const uint4* encg = (const uint4*)((const uint32_t*)g_ench + (long)bid * ENCH_U32);
        uint4* sE4 = (uint4*)sE;
        for (int i = t; i < ENCH_U32 / 4; i += NTHR) sE4[i] = encg[i];
        for (int i = t; i < 512; i += NTHR) s_wa[i] = Wattn[i];
    }

    // dec0 from init h2 (hist slot 0)
    ddec_phase(0, pool);
    grid_barrier();

    for (int s = 0; s < SS; s++) {
        // ======== phase A: attention + softmax + awe + x1/x2 build (block = batch) ========
        {
            const int b = bid;
            uint32_t* x1u = (uint32_t*)g_x1h + (long)b * 832;
            uint32_t* x2u = (uint32_t*)g_x2h + (long)b * 512;
            const int prev = (s == 0) ? 0 : (s - 1);
            // issue dec load FIRST (L2 latency overlaps the copies below)
            for (int i = t; i < 512; i += NTHR) s_dec[i] = g_dec[b * 512 + i];
            // x1 tail <- h1 halves (x2h front); x2 tail <- h2 halves (hist prev)
            x1u[576 + t] = x2u[t];
            x2u[256 + t] = histu[(long)prev * 32768 + b * 256 + t];
            __syncthreads();
            // attention logits from smem enc cache
            for (int p = warp; p < PP; p += 8) {
                const uint32_t* ep = sE + p * 256;
                uint32_t v[8];
#pragma unroll
                for (int i = 0; i < 8; i++) v[i] = ep[lane + 32 * i];
                float partial = 0.f;
#pragma unroll
                for (int i = 0; i < 8; i++) {
                    int a2 = lane + 32 * i;
                    __half2 h = *reinterpret_cast<__half2*>(&v[i]);
                    float2 f = __half22float2(h);
                    partial += tanh_fast(f.x + s_dec[2 * a2]) * s_wa[2 * a2];
                    partial += tanh_fast(f.y + s_dec[2 * a2 + 1]) * s_wa[2 * a2 + 1];
                }
#pragma unroll
                for (int o = 16; o > 0; o >>= 1) partial += __shfl_xor_sync(0xffffffffu, partial, o);
                if (lane == 0) s_attn[p] = partial;
            }
            __syncthreads();
            // softmax over P=196
            float v = (t < PP) ? s_attn[t] : -1e30f;
            float mx = v;
#pragma unroll
            for (int o = 16; o > 0; o >>= 1) mx = fmaxf(mx, __shfl_xor_sync(0xffffffffu, mx, o));
            if (lane == 0) s_red[warp] = mx;
            __syncthreads();
            if (t == 0) {
                float mm = s_red[0];
                for (int i = 1; i < 8; i++) mm = fmaxf(mm, s_red[i]);
                s_red[8] = mm;
            }
            __syncthreads();
            float m_all = s_red[8];
            float ev = (t < PP) ? __expf(v - m_all) : 0.f;
            float sum = ev;
#pragma unroll
            for (int o = 16; o > 0; o >>= 1) sum += __shfl_xor_sync(0xffffffffu, sum, o);
            __syncthreads();
            if (lane == 0) s_red[warp] = sum;
            __syncthreads();
            if (t == 0) {
                float ss = 0.f;
                for (int i = 0; i < 8; i++) ss += s_red[i];
                s_red[8] = 1.0f / ss;
            }
            __syncthreads();
            float inv = s_red[8];
            if (t < PP) {
                float al = ev * inv;
                s_attn[t] = al;
                alphas[((long)b * SS + s) * PP + t] = al;
            }
            __syncthreads();
            // awe = alpha @ features (fp16 stream, fp32 accum; unroll-4 for MLP)
            const uint32_t* fb = (const uint32_t*)g_feath + (long)b * PP * 512;
            float a0 = 0.f, a1 = 0.f, a2 = 0.f, a3 = 0.f;
#pragma unroll 4
            for (int p = 0; p < PP; p += 2) {
                uint32_t u0 = fb[(long)p * 512 + t];
                uint32_t u1 = fb[(long)p * 512 + t + 256];
                uint32_t u2 = fb[(long)(p + 1) * 512 + t];
                uint32_t u3 = fb[(long)(p + 1) * 512 + t + 256];
                float al0 = s_attn[p], al1 = s_attn[p + 1];
                float2 f0 = __half22float2(*reinterpret_cast<__half2*>(&u0));
                float2 f1 = __half22float2(*reinterpret_cast<__half2*>(&u1));
                float2 f2 = __half22float2(*reinterpret_cast<__half2*>(&u2));
                float2 f3 = __half22float2(*reinterpret_cast<__half2*>(&u3));
                a0 += al0 * f0.x + al1 * f2.x;
                a1 += al0 * f0.y + al1 * f2.y;
                a2 += al0 * f1.x + al1 * f3.x;
                a3 += al0 * f1.y + al1 * f3.y;
            }
            x1u[64 + t] = pack_h2(a0, a1);
            x1u[64 + 256 + t] = pack_h2(a2, a3);
            if (t < 64) {
                int tok = latex[b * LL + s];
                x1u[t] = pack_h2(emb[(long)tok * TT + 2 * t], emb[(long)tok * TT + 2 * t + 1]);
            }
            __syncthreads();
        }
        grid_barrier();
        // ======== phase B: gates1 + cell1 (h1n halves -> x2h front) ========
        lstm_phase(g_x1h, 832, g_W1h, g_b1, 832, g_c1, g_x2h, 1024, pool);
        grid_barrier();
        // ======== phase C: gates2 + cell2 (h2 halves -> hist[s]) ========
        lstm_phase(g_x2h, 512, g_W2h, g_b2, 512, g_c2, g_hist + (long)s * 65536, 512, pool);
        grid_barrier();
        // ======== phase D: dec only (32 blocks) ========
        ddec_phase(s, pool);
        grid_barrier();
    }
}

// ---------------- host launch ----------------
template <typename Sym>
static float* sym_addr(const Sym& s) {
    void* p = nullptr;
    cudaGetSymbolAddress(&p, s);
    return (float*)p;
}

extern "C" void kernel_launch(void* const* d_in, const int* in_sizes, int n_in,
                              void* d_out, int out_size) {
    const float* feat  = (const float*)d_in[0];
    const int*   latex = (const int*)d_in[1];
    const float* emb   = (const float*)d_in[2];
    const float* Wenc  = (const float*)d_in[3];
    const float* benc  = (const float*)d_in[4];
    const float* Wdec  = (const float*)d_in[5];
    const float* bdec  = (const float*)d_in[6];
    const float* Wattn = (const float*)d_in[7];
    const float* W1ih  = (const float*)d_in[9];
    const float* W1hh  = (const float*)d_in[10];
    const float* b1ih  = (const float*)d_in[11];
    const float* b1hh  = (const float*)d_in[12];
    const float* W2ih  = (const float*)d_in[13];
    const float* W2hh  = (const float*)d_in[14];
    const float* b2ih  = (const float*)d_in[15];
    const float* b2hh  = (const float*)d_in[16];
    const float* Wh0   = (const float*)d_in[17];
    const float* bh0   = (const float*)d_in[18];
    const float* Wc0   = (const float*)d_in[19];
    const float* bc0   = (const float*)d_in[20];
    const float* Wf    = (const float*)d_in[23];
    const float* bf    = (const float*)d_in[24];

    float* preds  = (float*)d_out;                  // [B, S, V]
    float* alphas = preds + (long)BB * SS * VV;     // [B, S, P]

    float* pMean  = sym_addr(g_mean);
    float* pHc    = sym_addr(g_hc);
    float* pWhct  = sym_addr(g_Whct);
    float* pBhc   = sym_addr(g_bhc);

    // opt-in to large dynamic smem for the decoder (immediate, not a stream op)
    cudaFuncSetAttribute(decoder_kernel, cudaFuncAttributeMaxDynamicSharedMemorySize, DYN_BYTES);

    // ---- prologue ----
    prep_kernel<<<512, 256>>>(W1ih, W1hh, W2ih, W2hh, Wf, Wdec, Wenc, Wh0, Wc0,
                              b1ih, b1hh, b2ih, b2hh, bf, bdec, bh0, bc0);
    featconv_kernel<<<512, 256>>>(feat);
    mean_kernel<<<128, 256>>>(feat);
    gemm_kernel<<<dim3(1024 / 16, 1), 128>>>(pMean, EE, pWhct, 1024, pBhc, pHc, 1024, 1024, EE);
    enc_mma_kernel<<<dim3(8, 784), NTHR>>>(benc);
    init_kernel<<<128, 512>>>();

    // ---- persistent decode loop (alphas in-loop; preds batched below) ----
    decoder_kernel<<<NBLK, NTHR, DYN_BYTES>>>(latex, emb, Wattn, alphas);

    // ---- batched preds epilogue: [32768 x 1000] = hist @ Wf ----
    preds_kernel<<<dim3(16, 1024), NTHR>>>(preds);
}

// round 13
// speedup vs baseline: 1.0413x; 1.0413x over previous
#include <cuda_runtime.h>
#include <cuda_fp16.h>
#include <cstdint>

#define BB 128   // batch
#define PP 196   // pixels
#define EE 1024  // encoder dim
#define DD 512   // decoder hidden
#define AA 512   // attention hidden
#define TT 128   // token emb
#define VV 1000  // vocab
#define SS 256   // steps
#define LL 257   // latex length

#define NBLK 128
#define NTHR 256

#define AS2_STRIDE 36
#define WS2_STRIDE 72
#define POOL_U32 (32 * AS2_STRIDE + 32 * WS2_STRIDE)   // 3456 u32 = 13.8 KB static

// dynamic smem: ench cache (50176 u32) + s_dec(512f) + s_wa(512f) + s_attn(208f) + s_red(16f)
#define ENCH_U32 50176
#define DYN_U32 (ENCH_U32 + 512 + 512 + 208 + 16)
#define DYN_BYTES (DYN_U32 * 4)

// ---------------- device-global scratch (static, no allocation) ----------------
__device__ __align__(16) __half g_ench[(long)BB * PP * AA];    // 25.7 MB enc_t fp16
__device__ __align__(16) __half g_feath[(long)BB * PP * EE];   // 51.5 MB features fp16
__device__ __align__(16) __half g_hist[(long)SS * BB * DD];    // 33.5 MB h2 history (fp16)
__device__ float g_mean[BB * EE];
__device__ float g_hc[BB * 2 * DD];
__device__ float g_c1[BB * DD], g_c2[BB * DD];
__device__ float g_dec[BB * AA];
// half2-k-packed activations
__device__ __align__(16) __half g_x1h[BB * 1664];   // [emb 0..127 | awe 128..1151 | h1 1152..1663]
__device__ __align__(16) __half g_x2h[BB * 1024];   // [h1n 0..511 | h2 512..1023]
// fp16 weights, half2-packed along k, u32 layout [K/2][NCOLS]
// W1h/W2h col permutation: storage col m: jj=m>>6, g=(m>>4)&3, dl=m&15 <-> gate row g*512+jj*16+dl
__device__ __align__(16) __half g_W1h[1664 * 2048];   // 6.8 MB
__device__ __align__(16) __half g_W2h[1024 * 2048];   // 4 MB
__device__ __align__(16) __half g_Wfdh[512 * 1536];   // cols: Wf(1000) | Wdec(512) | pad(24)
__device__ __align__(16) __half g_Weth[EE * AA];      // enc weights fp16
__device__ float g_Whct[EE * 2 * DD];                 // Wh0 | Wc0 fp32
__device__ float g_b1[2048], g_b2[2048], g_bfd[1536], g_bhc[2 * DD];

// tree-barrier state (padded counters on distinct L2 lines; monotonic gen -> replay safe)
__device__ unsigned g_cnt4[128];   // group g uses g_cnt4[g*32]
__device__ unsigned g_root = 0;
__device__ unsigned g_gen = 0;

__device__ __forceinline__ float tanh_fast(float x) {
    float y;
    asm("tanh.approx.f32 %0, %1;" : "=f"(y) : "f"(x));
    return y;
}
__device__ __forceinline__ float sigmoidf(float x) {
    return 1.0f / (1.0f + __expf(-x));
}
__device__ __forceinline__ uint32_t pack_h2(float a, float b) {
    __half2 h = __floats2half2_rn(a, b);
    return *reinterpret_cast<uint32_t*>(&h);
}

__device__ __forceinline__ void grid_barrier() {
    __syncthreads();
    if (threadIdx.x == 0) {
        __threadfence();
        unsigned gen = *(volatile unsigned*)&g_gen;   // read BEFORE arriving
        bool releaser = false;
        if (atomicAdd(&g_cnt4[(blockIdx.x & 3) * 32], 1u) == 31u) {
            if (atomicAdd(&g_root, 1u) == 3u) {
                atomicExch(&g_cnt4[0], 0u);
                atomicExch(&g_cnt4[32], 0u);
                atomicExch(&g_cnt4[64], 0u);
                atomicExch(&g_cnt4[96], 0u);
                atomicExch(&g_root, 0u);
                __threadfence();
                atomicAdd(&g_gen, 1u);
                releaser = true;
            }
        }
        if (!releaser) {
            while (*(volatile unsigned*)&g_gen == gen) { __nanosleep(128); }
        }
        __threadfence();
    }
    __syncthreads();
}

// ---------------- weight transposes + bias combine ----------------
__global__ void prep_kernel(const float* __restrict__ W1ih, const float* __restrict__ W1hh,
                            const float* __restrict__ W2ih, const float* __restrict__ W2hh,
                            const float* __restrict__ Wf, const float* __restrict__ Wdec,
                            const float* __restrict__ Wenc, const float* __restrict__ Wh0,
                            const float* __restrict__ Wc0,
                            const float* __restrict__ b1ih, const float* __restrict__ b1hh,
                            const float* __restrict__ b2ih, const float* __restrict__ b2hh,
                            const float* __restrict__ bf, const float* __restrict__ bdec,
                            const float* __restrict__ bh0, const float* __restrict__ bc0) {
    long tid = (long)blockIdx.x * blockDim.x + threadIdx.x;
    long nt = (long)gridDim.x * blockDim.x;
    for (long i = tid; i < 1664L * 2048; i += nt) {
        int k = (int)(i >> 11), m = (int)(i & 2047);
        int jj = m >> 6, g = (m >> 4) & 3, dl = m & 15;
        int r = g * 512 + jj * 16 + dl;
        float v = (k < 1152) ? W1ih[(long)r * 1152 + k] : W1hh[(long)r * 512 + (k - 1152)];
        g_W1h[((long)(k >> 1) * 2048 + m) * 2 + (k & 1)] = __float2half(v);
    }
    for (long i = tid; i < 1024L * 2048; i += nt) {
        int k = (int)(i >> 11), m = (int)(i & 2047);
        int jj = m >> 6, g = (m >> 4) & 3, dl = m & 15;
        int r = g * 512 + jj * 16 + dl;
        float v = (k < 512) ? W2ih[(long)r * 512 + k] : W2hh[(long)r * 512 + (k - 512)];
        g_W2h[((long)(k >> 1) * 2048 + m) * 2 + (k & 1)] = __float2half(v);
    }
    for (long i = tid; i < 512L * 1536; i += nt) {
        int k = (int)(i / 1536), n = (int)(i % 1536);
        float v = 0.f;
        if (n < 1000) v = Wf[(long)n * 512 + k];
        else if (n < 1512) v = Wdec[(long)(n - 1000) * 512 + k];
        g_Wfdh[((long)(k >> 1) * 1536 + n) * 2 + (k & 1)] = __float2half(v);
    }
    for (long i = tid; i < (long)EE * AA; i += nt) {
        int e = (int)(i >> 9), a = (int)(i & 511);
        g_Weth[((long)(e >> 1) * 512 + a) * 2 + (e & 1)] = __float2half(Wenc[(long)a * EE + e]);
    }
    for (long i = tid; i < (long)EE * 1024; i += nt) {
        int e = (int)(i >> 10), j = (int)(i & 1023);
        g_Whct[i] = (j < 512) ? Wh0[(long)j * EE + e] : Wc0[(long)(j - 512) * EE + e];
    }
    for (long i = tid; i < 2048; i += nt) {
        g_b1[i] = b1ih[i] + b1hh[i];
        g_b2[i] = b2ih[i] + b2hh[i];
    }
    for (long i = tid; i < 1536; i += nt)
        g_bfd[i] = (i < 1000) ? bf[i] : (i < 1512 ? bdec[i - 1000] : 0.f);
    for (long i = tid; i < 1024; i += nt)
        g_bhc[i] = (i < 512) ? bh0[i] : bc0[i - 512];
}

__global__ void featconv_kernel(const float* __restrict__ feat) {
    long tid = (long)blockIdx.x * blockDim.x + threadIdx.x;
    long nt = (long)gridDim.x * blockDim.x;
    uint32_t* out = (uint32_t*)g_feath;
    long n = (long)BB * PP * EE / 2;
    for (long i = tid; i < n; i += nt) {
        float2 f = *(const float2*)(feat + i * 2);
        out[i] = pack_h2(f.x, f.y);
    }
}

__global__ void mean_kernel(const float* __restrict__ feat) {
    int b = blockIdx.x, t = threadIdx.x;
    for (int e = t; e < EE; e += 256) {
        float acc = 0.f;
        const float* fb = feat + (long)b * PP * EE + e;
        for (int p = 0; p < PP; p++) acc += fb[(long)p * EE];
        g_mean[b * EE + e] = acc * (1.0f / 196.0f);
    }
}

// ---------------- fp32 SGEMM (prologue h0/c0 only) ----------------
__global__ __launch_bounds__(128)
void gemm_kernel(const float* __restrict__ Amat, int lda,
                 const float* __restrict__ W, int ldw,
                 const float* __restrict__ bias,
                 float* __restrict__ out1, long ldc1,
                 int N, int K) {
    __shared__ float As[32][128];
    __shared__ float Ws[32][16];
    int t = threadIdx.x;
    int n0 = blockIdx.x * 16;
    long m0 = (long)blockIdx.y * 128;
    int tr = t >> 2, tc = t & 3;
    int wk = t >> 2, wn = (t & 3) * 4;

    float acc[4][4];
#pragma unroll
    for (int i = 0; i < 4; i++)
#pragma unroll
        for (int j = 0; j < 4; j++) acc[i][j] = 0.f;

    for (int k0 = 0; k0 < K; k0 += 32) {
        const float4* Ap = (const float4*)(Amat + (m0 + t) * (long)lda + k0);
#pragma unroll
        for (int q = 0; q < 8; q++) {
            float4 a4 = Ap[q];
            As[q * 4 + 0][t] = a4.x;
            As[q * 4 + 1][t] = a4.y;
            As[q * 4 + 2][t] = a4.z;
            As[q * 4 + 3][t] = a4.w;
        }
        {
            float4 w4 = *(const float4*)(W + (long)(k0 + wk) * ldw + n0 + wn);
            *(float4*)&Ws[wk][wn] = w4;
        }
        __syncthreads();
#pragma unroll
        for (int k = 0; k < 32; k++) {
            float4 a4 = *(const float4*)&As[k][tr << 2];
            float4 w4 = *(const float4*)&Ws[k][tc << 2];
            float av[4] = {a4.x, a4.y, a4.z, a4.w};
            float wv[4] = {w4.x, w4.y, w4.z, w4.w};
#pragma unroll
            for (int i = 0; i < 4; i++)
#pragma unroll
                for (int j = 0; j < 4; j++) acc[i][j] += av[i] * wv[j];
        }
        __syncthreads();
    }
#pragma unroll
    for (int i = 0; i < 4; i++) {
        long m = m0 + (tr << 2) + i;
#pragma unroll
        for (int j = 0; j < 4; j++) {
            int n = n0 + (tc << 2) + j;
            if (n < N) out1[m * ldc1 + n] = acc[i][j] + bias[n];
        }
    }
}

// ================= fp16 MMA tile: C[32 x 64] = A[32 x K] @ W[K x 64slice] =================
__device__ __forceinline__ void mma32x64(const uint32_t* __restrict__ A2, int lda2, int mbase,
                                         const uint32_t* __restrict__ W2, int ldw2, int jbase,
                                         int K2, uint32_t* pool, float acc[2][4]) {
    uint32_t* As2 = pool;
    uint32_t* Ws2 = pool + 32 * AS2_STRIDE;
    const int t = threadIdx.x;
    const int warp = t >> 5, lane = t & 31;
    const int mw = warp >> 2, nw = warp & 3;
    const int gid = lane >> 2, tq = lane & 3;
    const int arow = t >> 3, ak = (t & 7) * 4;
    const int wk = t >> 3, wc = (t & 7) * 8;

#pragma unroll
    for (int nf = 0; nf < 2; nf++)
#pragma unroll
        for (int c = 0; c < 4; c++) acc[nf][c] = 0.f;

    uint4 aP = *(const uint4*)(A2 + (long)(mbase + arow) * lda2 + ak);
    uint4 wP0 = *(const uint4*)(W2 + (long)wk * ldw2 + jbase + wc);
    uint4 wP1 = *(const uint4*)(W2 + (long)wk * ldw2 + jbase + wc + 4);

    const int nT = K2 >> 5;
    for (int tile = 0; tile < nT; tile++) {
        *(uint4*)&As2[arow * AS2_STRIDE + ak] = aP;
        *(uint4*)&Ws2[wk * WS2_STRIDE + wc] = wP0;
        *(uint4*)&Ws2[wk * WS2_STRIDE + wc + 4] = wP1;
        if (tile + 1 < nT) {
            int kb = (tile + 1) * 32;
            aP = *(const uint4*)(A2 + (long)(mbase + arow) * lda2 + kb + ak);
            wP0 = *(const uint4*)(W2 + (long)(kb + wk) * ldw2 + jbase + wc);
            wP1 = *(const uint4*)(W2 + (long)(kb + wk) * ldw2 + jbase + wc + 4);
        }
        __syncthreads();
#pragma unroll
        for (int kk = 0; kk < 32; kk += 8) {
            int r = mw * 16 + gid;
            uint32_t a0 = As2[r * AS2_STRIDE + kk + tq];
            uint32_t a1 = As2[(r + 8) * AS2_STRIDE + kk + tq];
            uint32_t a2 = As2[r * AS2_STRIDE + kk + 4 + tq];
            uint32_t a3 = As2[(r + 8) * AS2_STRIDE + kk + 4 + tq];
#pragma unroll
            for (int nf = 0; nf < 2; nf++) {
                int cc = nw * 16 + nf * 8 + gid;
                uint32_t b0 = Ws2[(kk + tq) * WS2_STRIDE + cc];
                uint32_t b1 = Ws2[(kk + 4 + tq) * WS2_STRIDE + cc];
                asm volatile(
                    "mma.sync.aligned.m16n8k16.row.col.f32.f16.f16.f32 "
                    "{%0,%1,%2,%3}, {%4,%5,%6,%7}, {%8,%9}, {%0,%1,%2,%3};"
                    : "+f"(acc[nf][0]), "+f"(acc[nf][1]), "+f"(acc[nf][2]), "+f"(acc[nf][3])
                    : "r"(a0), "r"(a1), "r"(a2), "r"(a3), "r"(b0), "r"(b1));
            }
        }
        __syncthreads();
    }
}

// ================= gates GEMM + fused LSTM cell =================
// block (jj=bid>>2, mi=bid&3): batches mi*32..+31, hidden dims jj*16..+15
__device__ __forceinline__ void lstm_phase(const __half* __restrict__ Ah, int lda2,
                                           const __half* __restrict__ Wh,
                                           const float* __restrict__ bias, int K2,
                                           float* __restrict__ cst,
                                           __half* __restrict__ hcopy_h, int hstride,
                                           uint32_t* pool) {
    const int t = threadIdx.x;
    const int jj = blockIdx.x >> 2, mi = blockIdx.x & 3;
    const int mbase = mi * 32;
    const int warp = t >> 5, lane = t & 31;
    const int mw = warp >> 2, nw = warp & 3;
    const int gid = lane >> 2, tq = lane & 3;

    float acc[2][4];
    mma32x64((const uint32_t*)Ah, lda2, mbase, (const uint32_t*)Wh, 2048, jj * 64, K2, pool, acc);

    float* sg = (float*)pool;   // [32][65]
#pragma unroll
    for (int nf = 0; nf < 2; nf++)
#pragma unroll
        for (int c = 0; c < 4; c++) {
            int row = mw * 16 + gid + ((c & 2) ? 8 : 0);
            int col = nw * 16 + nf * 8 + 2 * tq + (c & 1);
            sg[row * 65 + col] = acc[nf][c];
        }
    __syncthreads();
#pragma unroll
    for (int r = 0; r < 2; r++) {
        int idx = t + 256 * r;
        int bl = idx >> 4, dl = idx & 15;
        int b = mbase + bl;
        int d = jj * 16 + dl;
        float gi = sg[bl * 65 + 0 + dl]  + bias[0 * 512 + d];
        float gf = sg[bl * 65 + 16 + dl] + bias[1 * 512 + d];
        float gg = sg[bl * 65 + 32 + dl] + bias[2 * 512 + d];
        float go = sg[bl * 65 + 48 + dl] + bias[3 * 512 + d];
        float cn = sigmoidf(gf) * cst[b * 512 + d] + sigmoidf(gi) * tanhf(gg);
        float hn = sigmoidf(go) * tanhf(cn);
        cst[b * 512 + d] = cn;
        hcopy_h[(long)b * hstride + d] = __float2half(hn);
    }
    __syncthreads();
}

// ================= dec-only GEMM: dec = h2 @ Wdec + bdec (32 blocks) =================
__device__ __forceinline__ void ddec_phase(int slot, uint32_t* pool) {
    const int bid = blockIdx.x;
    if (bid >= 32) return;
    const int t = threadIdx.x;
    const int jj = bid >> 2, mi = bid & 3;
    const int warp = t >> 5, lane = t & 31;
    const int mw = warp >> 2, nw = warp & 3;
    const int gid = lane >> 2, tq = lane & 3;

    float acc[2][4];
    mma32x64((const uint32_t*)g_hist + (long)slot * 32768, 256, mi * 32,
             (const uint32_t*)g_Wfdh, 1536, 1000 + jj * 64, 256, pool, acc);

#pragma unroll
    for (int nf = 0; nf < 2; nf++)
#pragma unroll
        for (int c = 0; c < 4; c++) {
            int m = mi * 32 + mw * 16 + gid + ((c & 2) ? 8 : 0);
            int col = jj * 64 + nw * 16 + nf * 8 + 2 * tq + (c & 1);   // 0..511
            g_dec[m * 512 + col] = acc[nf][c] + g_bfd[1000 + col];
        }
}

// ================= epilogue: preds[b][s][:] = hist[s][b] @ Wf + bf =================
__global__ __launch_bounds__(NTHR)
void preds_kernel(float* __restrict__ preds) {
    __shared__ __align__(16) uint32_t pool[POOL_U32];
    const int t = threadIdx.x;
    const int jj = blockIdx.x;          // 16 (cols jj*64..+63; >=1000 masked)
    const int mt = blockIdx.y;          // 1024 (rows mt*32..+31 of 32768)
    const int warp = t >> 5, lane = t & 31;
    const int mw = warp >> 2, nw = warp & 3;
    const int gid = lane >> 2, tq = lane & 3;

    float acc[2][4];
    mma32x64((const uint32_t*)g_hist, 256, mt * 32,
             (const uint32_t*)g_Wfdh, 1536, jj * 64, 256, pool, acc);

#pragma unroll
    for (int nf = 0; nf < 2; nf++)
#pragma unroll
        for (int c = 0; c < 4; c++) {
            int m = mt * 32 + mw * 16 + gid + ((c & 2) ? 8 : 0);
            int col = jj * 64 + nw * 16 + nf * 8 + 2 * tq + (c & 1);
            if (col < 1000) {
                int s = m >> 7, b = m & 127;
                preds[((long)b * SS + s) * VV + col] = acc[nf][c] + g_bfd[col];
            }
        }
}

// ================= prologue enc GEMM: ench = feath @ Weth + benc =================
__global__ __launch_bounds__(NTHR)
void enc_mma_kernel(const float* __restrict__ benc) {
    __shared__ __align__(16) uint32_t pool[POOL_U32];
    const int t = threadIdx.x;
    const int jj = blockIdx.x;          // 8
    const int mt = blockIdx.y;          // 784
    const int warp = t >> 5, lane = t & 31;
    const int mw = warp >> 2, nw = warp & 3;
    const int gid = lane >> 2, tq = lane & 3;

    float acc[2][4];
    mma32x64((const uint32_t*)g_feath, 512, mt * 32, (const uint32_t*)g_Weth, 512, jj * 64,
             512, pool, acc);

    uint32_t* out = (uint32_t*)g_ench;
#pragma unroll
    for (int nf = 0; nf < 2; nf++) {
        int cb = jj * 64 + nw * 16 + nf * 8 + 2 * tq;
        int r0 = mt * 32 + mw * 16 + gid;
        out[(long)r0 * 256 + (cb >> 1)] =
            pack_h2(acc[nf][0] + benc[cb], acc[nf][1] + benc[cb + 1]);
        out[(long)(r0 + 8) * 256 + (cb >> 1)] =
            pack_h2(acc[nf][2] + benc[cb], acc[nf][3] + benc[cb + 1]);
    }
}

// ================= persistent decoder kernel =================
__global__ __launch_bounds__(NTHR, 1)
void decoder_kernel(const int* __restrict__ latex, const float* __restrict__ emb,
                    const float* __restrict__ Wattn, float* __restrict__ alphas) {
    extern __shared__ __align__(16) uint32_t dyn[];
    __shared__ __align__(16) uint32_t pool[POOL_U32];
    uint32_t* sE = dyn;                          // ench cache [196][256] u32
    float* s_dec  = (float*)(dyn + ENCH_U32);    // 512
    float* s_wa   = s_dec + 512;                 // 512
    float* s_attn = s_wa + 512;                  // 208
    float* s_red  = s_attn + 208;                // 16
    const int t = threadIdx.x;
    const int bid = blockIdx.x;
    const int warp = t >> 5, lane = t & 31;
    const uint32_t* histu = (const uint32_t*)g_hist;

    // ---- folded init: block b spreads its own h0/c0 (was init_kernel) ----
    {
        const int b = bid;
        for (int d = t; d < 512; d += NTHR) {
            float h = g_hc[b * 1024 + d];
            float c = g_hc[b * 1024 + 512 + d];
            g_c1[b * 512 + d] = c;
            g_c2[b * 512 + d] = c;
            g_x2h[b * 1024 + d] = __float2half(h);   // h1 init (x2h front)
            g_hist[b * 512 + d] = __float2half(h);   // h2 init (hist slot 0)
        }
    }
    // one-time: cache this batch's enc_t slice + Wattn in smem (block-local, overlaps)
    {
        const uint4* encg = (const uint4*)((const uint32_t*)g_ench + (long)bid * ENCH_U32);
        uint4* sE4 = (uint4*)sE;
        for (int i = t; i < ENCH_U32 / 4; i += NTHR) sE4[i] = encg[i];
        for (int i = t; i < 512; i += NTHR) s_wa[i] = Wattn[i];
    }
    grid_barrier();   // hist[0]/c-state visible to all blocks

    // dec0 from init h2 (hist slot 0)
    ddec_phase(0, pool);
    grid_barrier();

    for (int s = 0; s < SS; s++) {
        // ======== phase A: attention + softmax + awe + x1/x2 build (block = batch) ========
        {
            const int b = bid;
            uint32_t* x1u = (uint32_t*)g_x1h + (long)b * 832;
            uint32_t* x2u = (uint32_t*)g_x2h + (long)b * 512;
            const int prev = (s == 0) ? 0 : (s - 1);
            // x1 tail <- h1 halves (x2h front, from B(s-1)/init); x2 tail <- h2 halves (hist prev)
            x1u[576 + t] = x2u[t];
            x2u[256 + t] = histu[(long)prev * 32768 + b * 256 + t];
            for (int i = t; i < 512; i += NTHR) s_dec[i] = g_dec[b * 512 + i];
            __syncthreads();
            // attention logits from smem enc cache
            for (int p = warp; p < PP; p += 8) {
                const uint32_t* ep = sE + p * 256;
                uint32_t v[8];
#pragma unroll
                for (int i = 0; i < 8; i++) v[i] = ep[lane + 32 * i];
                float partial = 0.f;
#pragma unroll
                for (int i = 0; i < 8; i++) {
                    int a2 = lane + 32 * i;
                    __half2 h = *reinterpret_cast<__half2*>(&v[i]);
                    float2 f = __half22float2(h);
                    partial += tanh_fast(f.x + s_dec[2 * a2]) * s_wa[2 * a2];
                    partial += tanh_fast(f.y + s_dec[2 * a2 + 1]) * s_wa[2 * a2 + 1];
                }
#pragma unroll
                for (int o = 16; o > 0; o >>= 1) partial += __shfl_xor_sync(0xffffffffu, partial, o);
                if (lane == 0) s_attn[p] = partial;
            }
            __syncthreads();
            // softmax over P=196
            float v = (t < PP) ? s_attn[t] : -1e30f;
            float mx = v;
#pragma unroll
            for (int o = 16; o > 0; o >>= 1) mx = fmaxf(mx, __shfl_xor_sync(0xffffffffu, mx, o));
            if (lane == 0) s_red[warp] = mx;
            __syncthreads();
            if (t == 0) {
                float mm = s_red[0];
                for (int i = 1; i < 8; i++) mm = fmaxf(mm, s_red[i]);
                s_red[8] = mm;
            }
            __syncthreads();
            float m_all = s_red[8];
            float ev = (t < PP) ? __expf(v - m_all) : 0.f;
            float sum = ev;
#pragma unroll
            for (int o = 16; o > 0; o >>= 1) sum += __shfl_xor_sync(0xffffffffu, sum, o);
            __syncthreads();
            if (lane == 0) s_red[warp] = sum;
            __syncthreads();
            if (t == 0) {
                float ss = 0.f;
                for (int i = 0; i < 8; i++) ss += s_red[i];
                s_red[8] = 1.0f / ss;
            }
            __syncthreads();
            float inv = s_red[8];
            if (t < PP) {
                float al = ev * inv;
                s_attn[t] = al;
                alphas[((long)b * SS + s) * PP + t] = al;
            }
            __syncthreads();
            // awe = alpha @ features (fp16 stream, fp32 accum)
            const uint32_t* fb = (const uint32_t*)g_feath + (long)b * PP * 512;
            float a0 = 0.f, a1 = 0.f, a2 = 0.f, a3 = 0.f;
            for (int p = 0; p < PP; p += 2) {
                uint32_t u0 = fb[(long)p * 512 + t];
                uint32_t u1 = fb[(long)p * 512 + t + 256];
                uint32_t u2 = fb[(long)(p + 1) * 512 + t];
                uint32_t u3 = fb[(long)(p + 1) * 512 + t + 256];
                float al0 = s_attn[p], al1 = s_attn[p + 1];
                float2 f0 = __half22float2(*reinterpret_cast<__half2*>(&u0));
                float2 f1 = __half22float2(*reinterpret_cast<__half2*>(&u1));
                float2 f2 = __half22float2(*reinterpret_cast<__half2*>(&u2));
                float2 f3 = __half22float2(*reinterpret_cast<__half2*>(&u3));
                a0 += al0 * f0.x + al1 * f2.x;
                a1 += al0 * f0.y + al1 * f2.y;
                a2 += al0 * f1.x + al1 * f3.x;
                a3 += al0 * f1.y + al1 * f3.y;
            }
            x1u[64 + t] = pack_h2(a0, a1);
            x1u[64 + 256 + t] = pack_h2(a2, a3);
            if (t < 64) {
                int tok = latex[b * LL + s];
                x1u[t] = pack_h2(emb[(long)tok * TT + 2 * t], emb[(long)tok * TT + 2 * t + 1]);
            }
            __syncthreads();
        }
        grid_barrier();
        // ======== phase B: gates1 + cell1 (h1n halves -> x2h front) ========
        lstm_phase(g_x1h, 832, g_W1h, g_b1, 832, g_c1, g_x2h, 1024, pool);
        grid_barrier();
        // ======== phase C: gates2 + cell2 (h2 halves -> hist[s]) ========
        lstm_phase(g_x2h, 512, g_W2h, g_b2, 512, g_c2, g_hist + (long)s * 65536, 512, pool);
        grid_barrier();
        // ======== phase D: dec only (32 blocks) ========
        ddec_phase(s, pool);
        grid_barrier();
    }
}

// ---------------- host launch ----------------
template <typename Sym>
static float* sym_addr(const Sym& s) {
    void* p = nullptr;
    cudaGetSymbolAddress(&p, s);
    return (float*)p;
}

extern "C" void kernel_launch(void* const* d_in, const int* in_sizes, int n_in,
                              void* d_out, int out_size) {
    const float* feat  = (const float*)d_in[0];
    const int*   latex = (const int*)d_in[1];
    const float* emb   = (const float*)d_in[2];
    const float* Wenc  = (const float*)d_in[3];
    const float* benc  = (const float*)d_in[4];
    const float* Wdec  = (const float*)d_in[5];
    const float* bdec  = (const float*)d_in[6];
    const float* Wattn = (const float*)d_in[7];
    const float* W1ih  = (const float*)d_in[9];
    const float* W1hh  = (const float*)d_in[10];
    const float* b1ih  = (const float*)d_in[11];
    const float* b1hh  = (const float*)d_in[12];
    const float* W2ih  = (const float*)d_in[13];
    const float* W2hh  = (const float*)d_in[14];
    const float* b2ih  = (const float*)d_in[15];
    const float* b2hh  = (const float*)d_in[16];
    const float* Wh0   = (const float*)d_in[17];
    const float* bh0   = (const float*)d_in[18];
    const float* Wc0   = (const float*)d_in[19];
    const float* bc0   = (const float*)d_in[20];
    const float* Wf    = (const float*)d_in[23];
    const float* bf    = (const float*)d_in[24];

    float* preds  = (float*)d_out;                  // [B, S, V]
    float* alphas = preds + (long)BB * SS * VV;     // [B, S, P]

    float* pMean  = sym_addr(g_mean);
    float* pHc    = sym_addr(g_hc);
    float* pWhct  = sym_addr(g_Whct);
    float* pBhc   = sym_addr(g_bhc);

    // opt-in to large dynamic smem for the decoder (immediate, not a stream op)
    cudaFuncSetAttribute(decoder_kernel, cudaFuncAttributeMaxDynamicSharedMemorySize, DYN_BYTES);

    // ---- prologue (5 launches -> decoder is launch index 5: ncu -s 5 -c 1 captures it) ----
    prep_kernel<<<512, 256>>>(W1ih, W1hh, W2ih, W2hh, Wf, Wdec, Wenc, Wh0, Wc0,
                              b1ih, b1hh, b2ih, b2hh, bf, bdec, bh0, bc0);
    featconv_kernel<<<512, 256>>>(feat);
    mean_kernel<<<128, 256>>>(feat);
    gemm_kernel<<<dim3(1024 / 16, 1), 128>>>(pMean, EE, pWhct, 1024, pBhc, pHc, 1024, 1024, EE);
    enc_mma_kernel<<<dim3(8, 784), NTHR>>>(benc);

    // ---- persistent decode loop (init folded in; alphas in-loop; preds batched below) ----
    decoder_kernel<<<NBLK, NTHR, DYN_BYTES>>>(latex, emb, Wattn, alphas);

    // ---- batched preds epilogue: [32768 x 1000] = hist @ Wf ----
    preds_kernel<<<dim3(16, 1024), NTHR>>>(preds);
}

// round 14
// speedup vs baseline: 1.1167x; 1.0725x over previous
#include <cuda_runtime.h>
#include <cuda_fp16.h>
#include <cstdint>

#define BB 128   // batch
#define PP 196   // pixels
#define EE 1024  // encoder dim
#define DD 512   // decoder hidden
#define AA 512   // attention hidden
#define TT 128   // token emb
#define VV 1000  // vocab
#define SS 256   // steps
#define LL 257   // latex length

#define NBLK 128
#define NTHR 256

#define AS2_STRIDE 36
#define WS2_STRIDE 72
#define POOL_U32 (32 * AS2_STRIDE + 32 * WS2_STRIDE)   // 3456 u32 = 13.8 KB static

// dynamic smem: ench cache (50176 u32) + s_dec(512f) + s_wa(512f) + s_attn(208f) + s_red(16f)
#define ENCH_U32 50176
#define DYN_U32 (ENCH_U32 + 512 + 512 + 208 + 16)
#define DYN_BYTES (DYN_U32 * 4)

// ---------------- device-global scratch (static, no allocation) ----------------
__device__ __align__(16) __half g_ench[(long)BB * PP * AA];    // 25.7 MB enc_t fp16
__device__ __align__(16) __half g_feath[(long)BB * PP * EE];   // 51.5 MB features fp16
__device__ __align__(16) __half g_hist[(long)SS * BB * DD];    // 33.5 MB h2 history (fp16)
__device__ float g_mean[BB * EE];
__device__ float g_hc[BB * 2 * DD];
__device__ float g_c1[BB * DD], g_c2[BB * DD];
__device__ float g_dec[BB * AA];
// half2-k-packed activations
__device__ __align__(16) __half g_x1h[BB * 1664];   // [emb 0..127 | awe 128..1151 | h1 1152..1663]
__device__ __align__(16) __half g_x2h[BB * 1024];   // [h1n 0..511 | h2 512..1023]
// fp16 weights, half2-packed along k, u32 layout [K/2][NCOLS]
// W1h/W2h col permutation: storage col m: jj=m>>6, g=(m>>4)&3, dl=m&15 <-> gate row g*512+jj*16+dl
__device__ __align__(16) __half g_W1h[1664 * 2048];   // 6.8 MB
__device__ __align__(16) __half g_W2h[1024 * 2048];   // 4 MB
__device__ __align__(16) __half g_Wfdh[512 * 1536];   // cols: Wf(1000) | Wdec(512) | pad(24)
__device__ __align__(16) __half g_Weth[EE * AA];      // enc weights fp16
__device__ float g_Whct[EE * 2 * DD];                 // Wh0 | Wc0 fp32
__device__ float g_b1[2048], g_b2[2048], g_bfd[1536], g_bhc[2 * DD];

// per-group barrier state (padded counters on distinct L2 lines; monotonic gen -> replay safe)
__device__ unsigned g_gcnt[4 * 32];   // group g uses g_gcnt[g*32]
__device__ unsigned g_ggen[4 * 32];   // group g uses g_ggen[g*32]

__device__ __forceinline__ float tanh_fast(float x) {
    float y;
    asm("tanh.approx.f32 %0, %1;" : "=f"(y) : "f"(x));
    return y;
}
__device__ __forceinline__ float sigmoidf(float x) {
    return 1.0f / (1.0f + __expf(-x));
}
__device__ __forceinline__ uint32_t pack_h2(float a, float b) {
    __half2 h = __floats2half2_rn(a, b);
    return *reinterpret_cast<uint32_t*>(&h);
}

// 32-block group barrier: blocks g*32..g*32+31 rendezvous independently of other groups
__device__ __forceinline__ void group_barrier(int grp) {
    __syncthreads();
    if (threadIdx.x == 0) {
        __threadfence();
        unsigned gen = *(volatile unsigned*)&g_ggen[grp * 32];   // read BEFORE arriving
        if (atomicAdd(&g_gcnt[grp * 32], 1u) == 31u) {
            atomicExch(&g_gcnt[grp * 32], 0u);
            __threadfence();
            atomicAdd(&g_ggen[grp * 32], 1u);
        } else {
            while (*(volatile unsigned*)&g_ggen[grp * 32] == gen) { __nanosleep(128); }
        }
        __threadfence();
    }
    __syncthreads();
}

// ---------------- weight transposes + bias combine ----------------
__global__ void prep_kernel(const float* __restrict__ W1ih, const float* __restrict__ W1hh,
                            const float* __restrict__ W2ih, const float* __restrict__ W2hh,
                            const float* __restrict__ Wf, const float* __restrict__ Wdec,
                            const float* __restrict__ Wenc, const float* __restrict__ Wh0,
                            const float* __restrict__ Wc0,
                            const float* __restrict__ b1ih, const float* __restrict__ b1hh,
                            const float* __restrict__ b2ih, const float* __restrict__ b2hh,
                            const float* __restrict__ bf, const float* __restrict__ bdec,
                            const float* __restrict__ bh0, const float* __restrict__ bc0) {
    long tid = (long)blockIdx.x * blockDim.x + threadIdx.x;
    long nt = (long)gridDim.x * blockDim.x;
    for (long i = tid; i < 1664L * 2048; i += nt) {
        int k = (int)(i >> 11), m = (int)(i & 2047);
        int jj = m >> 6, g = (m >> 4) & 3, dl = m & 15;
        int r = g * 512 + jj * 16 + dl;
        float v = (k < 1152) ? W1ih[(long)r * 1152 + k] : W1hh[(long)r * 512 + (k - 1152)];
        g_W1h[((long)(k >> 1) * 2048 + m) * 2 + (k & 1)] = __float2half(v);
    }
    for (long i = tid; i < 1024L * 2048; i += nt) {
        int k = (int)(i >> 11), m = (int)(i & 2047);
        int jj = m >> 6, g = (m >> 4) & 3, dl = m & 15;
        int r = g * 512 + jj * 16 + dl;
        float v = (k < 512) ? W2ih[(long)r * 512 + k] : W2hh[(long)r * 512 + (k - 512)];
        g_W2h[((long)(k >> 1) * 2048 + m) * 2 + (k & 1)] = __float2half(v);
    }
    for (long i = tid; i < 512L * 1536; i += nt) {
        int k = (int)(i / 1536), n = (int)(i % 1536);
        float v = 0.f;
        if (n < 1000) v = Wf[(long)n * 512 + k];
        else if (n < 1512) v = Wdec[(long)(n - 1000) * 512 + k];
        g_Wfdh[((long)(k >> 1) * 1536 + n) * 2 + (k & 1)] = __float2half(v);
    }
    for (long i = tid; i < (long)EE * AA; i += nt) {
        int e = (int)(i >> 9), a = (int)(i & 511);
        g_Weth[((long)(e >> 1) * 512 + a) * 2 + (e & 1)] = __float2half(Wenc[(long)a * EE + e]);
    }
    for (long i = tid; i < (long)EE * 1024; i += nt) {
        int e = (int)(i >> 10), j = (int)(i & 1023);
        g_Whct[i] = (j < 512) ? Wh0[(long)j * EE + e] : Wc0[(long)(j - 512) * EE + e];
    }
    for (long i = tid; i < 2048; i += nt) {
        g_b1[i] = b1ih[i] + b1hh[i];
        g_b2[i] = b2ih[i] + b2hh[i];
    }
    for (long i = tid; i < 1536; i += nt)
        g_bfd[i] = (i < 1000) ? bf[i] : (i < 1512 ? bdec[i - 1000] : 0.f);
    for (long i = tid; i < 1024; i += nt)
        g_bhc[i] = (i < 512) ? bh0[i] : bc0[i - 512];
}

__global__ void featconv_kernel(const float* __restrict__ feat) {
    long tid = (long)blockIdx.x * blockDim.x + threadIdx.x;
    long nt = (long)gridDim.x * blockDim.x;
    uint32_t* out = (uint32_t*)g_feath;
    long n = (long)BB * PP * EE / 2;
    for (long i = tid; i < n; i += nt) {
        float2 f = *(const float2*)(feat + i * 2);
        out[i] = pack_h2(f.x, f.y);
    }
}

__global__ void mean_kernel(const float* __restrict__ feat) {
    int b = blockIdx.x, t = threadIdx.x;
    for (int e = t; e < EE; e += 256) {
        float acc = 0.f;
        const float* fb = feat + (long)b * PP * EE + e;
        for (int p = 0; p < PP; p++) acc += fb[(long)p * EE];
        g_mean[b * EE + e] = acc * (1.0f / 196.0f);
    }
}

// ---------------- fp32 SGEMM (prologue h0/c0 only) ----------------
__global__ __launch_bounds__(128)
void gemm_kernel(const float* __restrict__ Amat, int lda,
                 const float* __restrict__ W, int ldw,
                 const float* __restrict__ bias,
                 float* __restrict__ out1, long ldc1,
                 int N, int K) {
    __shared__ float As[32][128];
    __shared__ float Ws[32][16];
    int t = threadIdx.x;
    int n0 = blockIdx.x * 16;
    long m0 = (long)blockIdx.y * 128;
    int tr = t >> 2, tc = t & 3;
    int wk = t >> 2, wn = (t & 3) * 4;

    float acc[4][4];
#pragma unroll
    for (int i = 0; i < 4; i++)
#pragma unroll
        for (int j = 0; j < 4; j++) acc[i][j] = 0.f;

    for (int k0 = 0; k0 < K; k0 += 32) {
        const float4* Ap = (const float4*)(Amat + (m0 + t) * (long)lda + k0);
#pragma unroll
        for (int q = 0; q < 8; q++) {
            float4 a4 = Ap[q];
            As[q * 4 + 0][t] = a4.x;
            As[q * 4 + 1][t] = a4.y;
            As[q * 4 + 2][t] = a4.z;
            As[q * 4 + 3][t] = a4.w;
        }
        {
            float4 w4 = *(const float4*)(W + (long)(k0 + wk) * ldw + n0 + wn);
            *(float4*)&Ws[wk][wn] = w4;
        }
        __syncthreads();
#pragma unroll
        for (int k = 0; k < 32; k++) {
            float4 a4 = *(const float4*)&As[k][tr << 2];
            float4 w4 = *(const float4*)&Ws[k][tc << 2];
            float av[4] = {a4.x, a4.y, a4.z, a4.w};
            float wv[4] = {w4.x, w4.y, w4.z, w4.w};
#pragma unroll
            for (int i = 0; i < 4; i++)
#pragma unroll
                for (int j = 0; j < 4; j++) acc[i][j] += av[i] * wv[j];
        }
        __syncthreads();
    }
#pragma unroll
    for (int i = 0; i < 4; i++) {
        long m = m0 + (tr << 2) + i;
#pragma unroll
        for (int j = 0; j < 4; j++) {
            int n = n0 + (tc << 2) + j;
            if (n < N) out1[m * ldc1 + n] = acc[i][j] + bias[n];
        }
    }
}

// ================= fp16 MMA tile: C[32 x 64] = A[32 x K] @ W[K x 64slice] =================
__device__ __forceinline__ void mma32x64(const uint32_t* __restrict__ A2, int lda2, int mbase,
                                         const uint32_t* __restrict__ W2, int ldw2, int jbase,
                                         int K2, uint32_t* pool, float acc[2][4]) {
    uint32_t* As2 = pool;
    uint32_t* Ws2 = pool + 32 * AS2_STRIDE;
    const int t = threadIdx.x;
    const int warp = t >> 5, lane = t & 31;
    const int mw = warp >> 2, nw = warp & 3;
    const int gid = lane >> 2, tq = lane & 3;
    const int arow = t >> 3, ak = (t & 7) * 4;
    const int wk = t >> 3, wc = (t & 7) * 8;

#pragma unroll
    for (int nf = 0; nf < 2; nf++)
#pragma unroll
        for (int c = 0; c < 4; c++) acc[nf][c] = 0.f;

    uint4 aP = *(const uint4*)(A2 + (long)(mbase + arow) * lda2 + ak);
    uint4 wP0 = *(const uint4*)(W2 + (long)wk * ldw2 + jbase + wc);
    uint4 wP1 = *(const uint4*)(W2 + (long)wk * ldw2 + jbase + wc + 4);

    const int nT = K2 >> 5;
    for (int tile = 0; tile < nT; tile++) {
        *(uint4*)&As2[arow * AS2_STRIDE + ak] = aP;
        *(uint4*)&Ws2[wk * WS2_STRIDE + wc] = wP0;
        *(uint4*)&Ws2[wk * WS2_STRIDE + wc + 4] = wP1;
        if (tile + 1 < nT) {
            int kb = (tile + 1) * 32;
            aP = *(const uint4*)(A2 + (long)(mbase + arow) * lda2 + kb + ak);
            wP0 = *(const uint4*)(W2 + (long)(kb + wk) * ldw2 + jbase + wc);
            wP1 = *(const uint4*)(W2 + (long)(kb + wk) * ldw2 + jbase + wc + 4);
        }
        __syncthreads();
#pragma unroll
        for (int kk = 0; kk < 32; kk += 8) {
            int r = mw * 16 + gid;
            uint32_t a0 = As2[r * AS2_STRIDE + kk + tq];
            uint32_t a1 = As2[(r + 8) * AS2_STRIDE + kk + tq];
            uint32_t a2 = As2[r * AS2_STRIDE + kk + 4 + tq];
            uint32_t a3 = As2[(r + 8) * AS2_STRIDE + kk + 4 + tq];
#pragma unroll
            for (int nf = 0; nf < 2; nf++) {
                int cc = nw * 16 + nf * 8 + gid;
                uint32_t b0 = Ws2[(kk + tq) * WS2_STRIDE + cc];
                uint32_t b1 = Ws2[(kk + 4 + tq) * WS2_STRIDE + cc];
                asm volatile(
                    "mma.sync.aligned.m16n8k16.row.col.f32.f16.f16.f32 "
                    "{%0,%1,%2,%3}, {%4,%5,%6,%7}, {%8,%9}, {%0,%1,%2,%3};"
                    : "+f"(acc[nf][0]), "+f"(acc[nf][1]), "+f"(acc[nf][2]), "+f"(acc[nf][3])
                    : "r"(a0), "r"(a1), "r"(a2), "r"(a3), "r"(b0), "r"(b1));
            }
        }
        __syncthreads();
    }
}

// ================= gates GEMM + fused LSTM cell =================
// caller passes jj (dim slice 0..31) and mbase (batch base of this group)
__device__ __forceinline__ void lstm_phase(int jj, int mbase,
                                           const __half* __restrict__ Ah, int lda2,
                                           const __half* __restrict__ Wh,
                                           const float* __restrict__ bias, int K2,
                                           float* __restrict__ cst,
                                           __half* __restrict__ hcopy_h, int hstride,
                                           uint32_t* pool) {
    const int t = threadIdx.x;
    const int warp = t >> 5, lane = t & 31;
    const int mw = warp >> 2, nw = warp & 3;
    const int gid = lane >> 2, tq = lane & 3;

    float acc[2][4];
    mma32x64((const uint32_t*)Ah, lda2, mbase, (const uint32_t*)Wh, 2048, jj * 64, K2, pool, acc);

    float* sg = (float*)pool;   // [32][65]
#pragma unroll
    for (int nf = 0; nf < 2; nf++)
#pragma unroll
        for (int c = 0; c < 4; c++) {
            int row = mw * 16 + gid + ((c & 2) ? 8 : 0);
            int col = nw * 16 + nf * 8 + 2 * tq + (c & 1);
            sg[row * 65 + col] = acc[nf][c];
        }
    __syncthreads();
#pragma unroll
    for (int r = 0; r < 2; r++) {
        int idx = t + 256 * r;
        int bl = idx >> 4, dl = idx & 15;
        int b = mbase + bl;
        int d = jj * 16 + dl;
        float gi = sg[bl * 65 + 0 + dl]  + bias[0 * 512 + d];
        float gf = sg[bl * 65 + 16 + dl] + bias[1 * 512 + d];
        float gg = sg[bl * 65 + 32 + dl] + bias[2 * 512 + d];
        float go = sg[bl * 65 + 48 + dl] + bias[3 * 512 + d];
        float cn = sigmoidf(gf) * cst[b * 512 + d] + sigmoidf(gi) * tanhf(gg);
        float hn = sigmoidf(go) * tanhf(cn);
        cst[b * 512 + d] = cn;
        hcopy_h[(long)b * hstride + d] = __float2half(hn);
    }
    __syncthreads();
}

// ================= dec-only GEMM: dec = h2 @ Wdec + bdec (8 slices per group) ========
__device__ __forceinline__ void ddec_phase(int jj, int mbase, int slot, uint32_t* pool) {
    if (jj >= 8) return;   // only 8 of 32 blocks per group have work
    const int t = threadIdx.x;
    const int warp = t >> 5, lane = t & 31;
    const int mw = warp >> 2, nw = warp & 3;
    const int gid = lane >> 2, tq = lane & 3;

    float acc[2][4];
    mma32x64((const uint32_t*)g_hist + (long)slot * 32768, 256, mbase,
             (const uint32_t*)g_Wfdh, 1536, 1000 + jj * 64, 256, pool, acc);

#pragma unroll
    for (int nf = 0; nf < 2; nf++)
#pragma unroll
        for (int c = 0; c < 4; c++) {
            int m = mbase + mw * 16 + gid + ((c & 2) ? 8 : 0);
            int col = jj * 64 + nw * 16 + nf * 8 + 2 * tq + (c & 1);   // 0..511
            g_dec[m * 512 + col] = acc[nf][c] + g_bfd[1000 + col];
        }
}

// ================= epilogue: preds[b][s][:] = hist[s][b] @ Wf + bf =================
__global__ __launch_bounds__(NTHR)
void preds_kernel(float* __restrict__ preds) {
    __shared__ __align__(16) uint32_t pool[POOL_U32];
    const int t = threadIdx.x;
    const int jj = blockIdx.x;          // 16 (cols jj*64..+63; >=1000 masked)
    const int mt = blockIdx.y;          // 1024 (rows mt*32..+31 of 32768)
    const int warp = t >> 5, lane = t & 31;
    const int mw = warp >> 2, nw = warp & 3;
    const int gid = lane >> 2, tq = lane & 3;

    float acc[2][4];
    mma32x64((const uint32_t*)g_hist, 256, mt * 32,
             (const uint32_t*)g_Wfdh, 1536, jj * 64, 256, pool, acc);

#pragma unroll
    for (int nf = 0; nf < 2; nf++)
#pragma unroll
        for (int c = 0; c < 4; c++) {
            int m = mt * 32 + mw * 16 + gid + ((c & 2) ? 8 : 0);
            int col = jj * 64 + nw * 16 + nf * 8 + 2 * tq + (c & 1);
            if (col < 1000) {
                int s = m >> 7, b = m & 127;
                preds[((long)b * SS + s) * VV + col] = acc[nf][c] + g_bfd[col];
            }
        }
}

// ================= prologue enc GEMM: ench = feath @ Weth + benc =================
__global__ __launch_bounds__(NTHR)
void enc_mma_kernel(const float* __restrict__ benc) {
    __shared__ __align__(16) uint32_t pool[POOL_U32];
    const int t = threadIdx.x;
    const int jj = blockIdx.x;          // 8
    const int mt = blockIdx.y;          // 784
    const int warp = t >> 5, lane = t & 31;
    const int mw = warp >> 2, nw = warp & 3;
    const int gid = lane >> 2, tq = lane & 3;

    float acc[2][4];
    mma32x64((const uint32_t*)g_feath, 512, mt * 32, (const uint32_t*)g_Weth, 512, jj * 64,
             512, pool, acc);

    uint32_t* out = (uint32_t*)g_ench;
#pragma unroll
    for (int nf = 0; nf < 2; nf++) {
        int cb = jj * 64 + nw * 16 + nf * 8 + 2 * tq;
        int r0 = mt * 32 + mw * 16 + gid;
        out[(long)r0 * 256 + (cb >> 1)] =
            pack_h2(acc[nf][0] + benc[cb], acc[nf][1] + benc[cb + 1]);
        out[(long)(r0 + 8) * 256 + (cb >> 1)] =
            pack_h2(acc[nf][2] + benc[cb], acc[nf][3] + benc[cb + 1]);
    }
}

// ================= persistent decoder kernel (4 independent 32-block pipelines) ======
__global__ __launch_bounds__(NTHR, 1)
void decoder_kernel(const int* __restrict__ latex, const float* __restrict__ emb,
                    const float* __restrict__ Wattn, float* __restrict__ alphas) {
    extern __shared__ __align__(16) uint32_t dyn[];
    __shared__ __align__(16) uint32_t pool[POOL_U32];
    uint32_t* sE = dyn;                          // ench cache [196][256] u32
    float* s_dec  = (float*)(dyn + ENCH_U32);    // 512
    float* s_wa   = s_dec + 512;                 // 512
    float* s_attn = s_wa + 512;                  // 208
    float* s_red  = s_attn + 208;                // 16
    const int t = threadIdx.x;
    const int bid = blockIdx.x;
    const int grp = bid >> 5;     // batch group 0..3 (batches grp*32..+31)
    const int jsl = bid & 31;     // dim slice for B/C (0..31); D uses jsl<8
    const int mbase = grp * 32;
    const int warp = t >> 5, lane = t & 31;
    const uint32_t* histu = (const uint32_t*)g_hist;

    // ---- folded init: block b spreads its own h0/c0 ----
    {
        const int b = bid;
        for (int d = t; d < 512; d += NTHR) {
            float h = g_hc[b * 1024 + d];
            float c = g_hc[b * 1024 + 512 + d];
            g_c1[b * 512 + d] = c;
            g_c2[b * 512 + d] = c;
            g_x2h[b * 1024 + d] = __float2half(h);   // h1 init (x2h front)
            g_hist[b * 512 + d] = __float2half(h);   // h2 init (hist slot 0)
        }
    }
    // one-time: cache this batch's enc_t slice + Wattn in smem
    {
        const uint4* encg = (const uint4*)((const uint32_t*)g_ench + (long)bid * ENCH_U32);
        uint4* sE4 = (uint4*)sE;
        for (int i = t; i < ENCH_U32 / 4; i += NTHR) sE4[i] = encg[i];
        for (int i = t; i < 512; i += NTHR) s_wa[i] = Wattn[i];
    }
    group_barrier(grp);   // group's hist[0]/c-state visible within group

    // dec0 from init h2 (hist slot 0)
    ddec_phase(jsl, mbase, 0, pool);
    group_barrier(grp);

    for (int s = 0; s < SS; s++) {
        // ======== phase A: attention + softmax + awe + x1/x2 build (block = batch) ========
        {
            const int b = bid;
            uint32_t* x1u = (uint32_t*)g_x1h + (long)b * 832;
            uint32_t* x2u = (uint32_t*)g_x2h + (long)b * 512;
            const int prev = (s == 0) ? 0 : (s - 1);
            // x1 tail <- h1 halves (x2h front); x2 tail <- h2 halves (hist prev)
            x1u[576 + t] = x2u[t];
            x2u[256 + t] = histu[(long)prev * 32768 + b * 256 + t];
            for (int i = t; i < 512; i += NTHR) s_dec[i] = g_dec[b * 512 + i];
            __syncthreads();
            // attention logits from smem enc cache
            for (int p = warp; p < PP; p += 8) {
                const uint32_t* ep = sE + p * 256;
                uint32_t v[8];
#pragma unroll
                for (int i = 0; i < 8; i++) v[i] = ep[lane + 32 * i];
                float partial = 0.f;
#pragma unroll
                for (int i = 0; i < 8; i++) {
                    int a2 = lane + 32 * i;
                    __half2 h = *reinterpret_cast<__half2*>(&v[i]);
                    float2 f = __half22float2(h);
                    partial += tanh_fast(f.x + s_dec[2 * a2]) * s_wa[2 * a2];
                    partial += tanh_fast(f.y + s_dec[2 * a2 + 1]) * s_wa[2 * a2 + 1];
                }
#pragma unroll
                for (int o = 16; o > 0; o >>= 1) partial += __shfl_xor_sync(0xffffffffu, partial, o);
                if (lane == 0) s_attn[p] = partial;
            }
            __syncthreads();
            // softmax over P=196
            float v = (t < PP) ? s_attn[t] : -1e30f;
            float mx = v;
#pragma unroll
            for (int o = 16; o > 0; o >>= 1) mx = fmaxf(mx, __shfl_xor_sync(0xffffffffu, mx, o));
            if (lane == 0) s_red[warp] = mx;
            __syncthreads();
            if (t == 0) {
                float mm = s_red[0];
                for (int i = 1; i < 8; i++) mm = fmaxf(mm, s_red[i]);
                s_red[8] = mm;
            }
            __syncthreads();
            float m_all = s_red[8];
            float ev = (t < PP) ? __expf(v - m_all) : 0.f;
            float sum = ev;
#pragma unroll
            for (int o = 16; o > 0; o >>= 1) sum += __shfl_xor_sync(0xffffffffu, sum, o);
            __syncthreads();
            if (lane == 0) s_red[warp] = sum;
            __syncthreads();
            if (t == 0) {
                float ss = 0.f;
                for (int i = 0; i < 8; i++) ss += s_red[i];
                s_red[8] = 1.0f / ss;
            }
            __syncthreads();
            float inv = s_red[8];
            if (t < PP) {
                float al = ev * inv;
                s_attn[t] = al;
                alphas[((long)b * SS + s) * PP + t] = al;
            }
            __syncthreads();
            // awe = alpha @ features (fp16 stream, fp32 accum)
            const uint32_t* fb = (const uint32_t*)g_feath + (long)b * PP * 512;
            float a0 = 0.f, a1 = 0.f, a2 = 0.f, a3 = 0.f;
            for (int p = 0; p < PP; p += 2) {
                uint32_t u0 = fb[(long)p * 512 + t];
                uint32_t u1 = fb[(long)p * 512 + t + 256];
                uint32_t u2 = fb[(long)(p + 1) * 512 + t];
                uint32_t u3 = fb[(long)(p + 1) * 512 + t + 256];
                float al0 = s_attn[p], al1 = s_attn[p + 1];
                float2 f0 = __half22float2(*reinterpret_cast<__half2*>(&u0));
                float2 f1 = __half22float2(*reinterpret_cast<__half2*>(&u1));
                float2 f2 = __half22float2(*reinterpret_cast<__half2*>(&u2));
                float2 f3 = __half22float2(*reinterpret_cast<__half2*>(&u3));
                a0 += al0 * f0.x + al1 * f2.x;
                a1 += al0 * f0.y + al1 * f2.y;
                a2 += al0 * f1.x + al1 * f3.x;
                a3 += al0 * f1.y + al1 * f3.y;
            }
            x1u[64 + t] = pack_h2(a0, a1);
            x1u[64 + 256 + t] = pack_h2(a2, a3);
            if (t < 64) {
                int tok = latex[b * LL + s];
                x1u[t] = pack_h2(emb[(long)tok * TT + 2 * t], emb[(long)tok * TT + 2 * t + 1]);
            }
            __syncthreads();
        }
        group_barrier(grp);
        // ======== phase B: gates1 + cell1 (h1n halves -> x2h front) ========
        lstm_phase(jsl, mbase, g_x1h, 832, g_W1h, g_b1, 832, g_c1, g_x2h, 1024, pool);
        group_barrier(grp);
        // ======== phase C: gates2 + cell2 (h2 halves -> hist[s]) ========
        lstm_phase(jsl, mbase, g_x2h, 512, g_W2h, g_b2, 512, g_c2,
                   g_hist + (long)s * 65536, 512, pool);
        group_barrier(grp);
        // ======== phase D: dec only (8 slices per group) ========
        ddec_phase(jsl, mbase, s, pool);
        group_barrier(grp);
    }
}

// ---------------- host launch ----------------
template <typename Sym>
static float* sym_addr(const Sym& s) {
    void* p = nullptr;
    cudaGetSymbolAddress(&p, s);
    return (float*)p;
}

extern "C" void kernel_launch(void* const* d_in, const int* in_sizes, int n_in,
                              void* d_out, int out_size) {
    const float* feat  = (const float*)d_in[0];
    const int*   latex = (const int*)d_in[1];
    const float* emb   = (const float*)d_in[2];
    const float* Wenc  = (const float*)d_in[3];
    const float* benc  = (const float*)d_in[4];
    const float* Wdec  = (const float*)d_in[5];
    const float* bdec  = (const float*)d_in[6];
    const float* Wattn = (const float*)d_in[7];
    const float* W1ih  = (const float*)d_in[9];
    const float* W1hh  = (const float*)d_in[10];
    const float* b1ih  = (const float*)d_in[11];
    const float* b1hh  = (const float*)d_in[12];
    const float* W2ih  = (const float*)d_in[13];
    const float* W2hh  = (const float*)d_in[14];
    const float* b2ih  = (const float*)d_in[15];
    const float* b2hh  = (const float*)d_in[16];
    const float* Wh0   = (const float*)d_in[17];
    const float* bh0   = (const float*)d_in[18];
    const float* Wc0   = (const float*)d_in[19];
    const float* bc0   = (const float*)d_in[20];
    const float* Wf    = (const float*)d_in[23];
    const float* bf    = (const float*)d_in[24];

    float* preds  = (float*)d_out;                  // [B, S, V]
    float* alphas = preds + (long)BB * SS * VV;     // [B, S, P]

    float* pMean  = sym_addr(g_mean);
    float* pHc    = sym_addr(g_hc);
    float* pWhct  = sym_addr(g_Whct);
    float* pBhc   = sym_addr(g_bhc);

    // opt-in to large dynamic smem for the decoder (immediate, not a stream op)
    cudaFuncSetAttribute(decoder_kernel, cudaFuncAttributeMaxDynamicSharedMemorySize, DYN_BYTES);

    // ---- prologue ----
    prep_kernel<<<512, 256>>>(W1ih, W1hh, W2ih, W2hh, Wf, Wdec, Wenc, Wh0, Wc0,
                              b1ih, b1hh, b2ih, b2hh, bf, bdec, bh0, bc0);
    featconv_kernel<<<512, 256>>>(feat);
    mean_kernel<<<128, 256>>>(feat);
    gemm_kernel<<<dim3(1024 / 16, 1), 128>>>(pMean, EE, pWhct, 1024, pBhc, pHc, 1024, 1024, EE);
    enc_mma_kernel<<<dim3(8, 784), NTHR>>>(benc);

    // ---- persistent decode loop: 4 independent 32-block group pipelines ----
    decoder_kernel<<<NBLK, NTHR, DYN_BYTES>>>(latex, emb, Wattn, alphas);

    // ---- batched preds epilogue: [32768 x 1000] = hist @ Wf ----
    preds_kernel<<<dim3(16, 1024), NTHR>>>(preds);
}